// round 1
// baseline (speedup 1.0000x reference)
#include <cuda_runtime.h>
#include <cstdint>

// DiceLoss histogram kernel for B200 (sm_100a).
//
// Strategy: 134 MB of int32 label reads -> memory bound (~18us floor).
// Avoid ALL histogram atomics in the hot loop: every lane owns a private
// 171-counter region in shared memory (3 histograms x 57 bins), laid out
// counter-major/lane-minor so the smem bank is always == lane (conflict-free).
// Per pair we read the 3 counters first, then write all 3 (the three index
// ranges are disjoint, so load/load/load + store/store/store is safe and keeps
// the three RMW chains overlapped instead of serialized).
//
// Reduction: warp REDUX across lanes (conflict-free reads), cross-warp sum in
// smem scratch, per-block partials to a __device__ array (fully overwritten
// every launch -> deterministic, no zeroing kernel, no global atomics), then a
// tiny finalize kernel computes 1 - mean(dice) over bins 1..56.

#define NBINS   57
#define NB3     171                      // 3 * 57 counters
#define NWARPS  8
#define TPB     256
#define CPW     (NB3 * 32)               // words per warp region = 5472
#define CNT_WORDS     (NWARPS * CPW)     // 43776
#define SCRATCH_WORDS (NWARPS * NB3)     // 1368
#define SMEM_WORDS    (CNT_WORDS + SCRATCH_WORDS)
#define SMEM_BYTES    (SMEM_WORDS * 4)   // 180,576 B (fits 227KB opt-in)
#define MAXBLK  256

__device__ int g_part[MAXBLK * NB3];     // per-block partial histograms

// One pair (p, t): increment 3 per-lane counters.
// wb points at (warp_region + lane); counter c lives at wb[c*32].
// Loads grouped before stores: the 3 addresses are always distinct
// (index ranges [0,57), [57,114), [114,171)), so this is exact.
__device__ __forceinline__ void proc(int* __restrict__ wb, int p, int t) {
    int* aP = wb + (p << 5);
    int* aT = wb + ((57 + t) << 5);
    int  m  = (p == t) ? p : 0;
    int* aI = wb + ((114 + m) << 5);
    int vP = *aP;
    int vT = *aT;
    int vI = *aI;
    *aP = vP + 1;
    *aT = vT + 1;
    *aI = vI + 1;
}

extern "C" __global__ void __launch_bounds__(TPB, 1)
hist_kernel(const int* __restrict__ pred, const int* __restrict__ targ, int n)
{
    extern __shared__ int sh[];
    int* scratch = sh + CNT_WORDS;

    const int tid  = threadIdx.x;
    const int lane = tid & 31;
    const int warp = tid >> 5;
    int* wb = sh + warp * CPW + lane;

    // Zero all counters + scratch.
    for (int i = tid; i < SMEM_WORDS; i += TPB) sh[i] = 0;
    __syncthreads();

    const int stride = gridDim.x * TPB;

    const bool aligned = ((((uintptr_t)pred) | ((uintptr_t)targ)) & 15u) == 0;
    if (aligned) {
        const int n4 = n >> 2;
        const int4* __restrict__ p4 = (const int4*)pred;
        const int4* __restrict__ t4 = (const int4*)targ;
        for (int i = blockIdx.x * TPB + tid; i < n4; i += stride) {
            int4 a = __ldg(p4 + i);
            int4 b = __ldg(t4 + i);
            proc(wb, a.x, b.x);
            proc(wb, a.y, b.y);
            proc(wb, a.z, b.z);
            proc(wb, a.w, b.w);
        }
        // tail (n not divisible by 4)
        for (int i = (n4 << 2) + blockIdx.x * TPB + tid; i < n; i += stride) {
            proc(wb, __ldg(pred + i), __ldg(targ + i));
        }
    } else {
        for (int i = blockIdx.x * TPB + tid; i < n; i += stride) {
            proc(wb, __ldg(pred + i), __ldg(targ + i));
        }
    }
    __syncthreads();

    // Phase 1: per-warp lane reduction. Reads are 32 consecutive words
    // (conflict-free); REDUX.SUM folds the 32 lanes.
    for (int c = 0; c < NB3; c++) {
        int v = sh[warp * CPW + c * 32 + lane];
        int s = __reduce_add_sync(0xffffffffu, v);
        if (lane == 0) scratch[warp * NB3 + c] = s;
    }
    __syncthreads();

    // Phase 2: cross-warp sum, write per-block partial (no atomics).
    if (tid < NB3) {
        int s = 0;
        #pragma unroll
        for (int w = 0; w < NWARPS; w++) s += scratch[w * NB3 + tid];
        g_part[blockIdx.x * NB3 + tid] = s;
    }
}

extern "C" __global__ void final_kernel(float* __restrict__ out, int nblocks)
{
    __shared__ float hh[NB3];
    __shared__ float dsum[64];
    const int t = threadIdx.x;

    if (t < NB3) {
        int s = 0;
        for (int b = 0; b < nblocks; b++) s += g_part[b * NB3 + t];
        hh[t] = (float)s;
    }
    __syncthreads();

    if (t < 64) {
        float v = 0.0f;
        if (t >= 1 && t < NBINS) {
            float inter = hh[114 + t];
            float uni   = hh[t] + hh[57 + t];
            v = 2.0f * inter / (uni + 1e-5f);
        }
        dsum[t] = v;
    }
    __syncthreads();

    if (t == 0) {
        float s = 0.0f;
        for (int i = 0; i < 64; i++) s += dsum[i];
        out[0] = 1.0f - s / (float)(NBINS - 1);
    }
}

extern "C" void kernel_launch(void* const* d_in, const int* in_sizes, int n_in,
                              void* d_out, int out_size)
{
    const int* pred = (const int*)d_in[0];
    const int* targ = (const int*)d_in[1];
    const int n = in_sizes[0];

    // Opt in to >48KB dynamic smem (idempotent; legal during capture).
    cudaFuncSetAttribute((const void*)hist_kernel,
                         cudaFuncAttributeMaxDynamicSharedMemorySize, SMEM_BYTES);

    int sms = 148;
    if (cudaDeviceGetAttribute(&sms, cudaDevAttrMultiProcessorCount, 0) != cudaSuccess)
        sms = 148;
    int grid = sms < MAXBLK ? sms : MAXBLK;
    if (grid < 1) grid = 1;

    hist_kernel<<<grid, TPB, SMEM_BYTES>>>(pred, targ, n);
    final_kernel<<<1, 192>>>((float*)d_out, grid);
}

// round 2
// speedup vs baseline: 1.6937x; 1.6937x over previous
#include <cuda_runtime.h>
#include <cstdint>

// DiceLoss (57-bin label histogram) for B200 sm_100a.
//
// R2: the R1 kernel was DRAM-latency-bound (1.7 TB/s achieved): one int4 pair
// in flight per thread. Fixes:
//  - unroll x4 with ALL 8 LDG.128 batched before histogram work (MLP 8/thread)
//  - u16 per-lane private counters -> 512 threads (16 warps) in one CTA
//  - parallel finalize kernel (coalesced, REDUX) instead of serial loops
//
// Per-lane privatization: lane l of warp w owns halfword sh16[w*5472 + c*32 + l]
// for counter c in [0,171) = {pred[57] | true[57] | inter[57]}. A warp access
// touches halves c*32+0..31 -> 16 words, 2 lanes/word, one word per bank pair:
// conflict-free, 64B per warp op. Max increments per counter = pairs/thread
// = 16.7M/(148*512) = 222 << 65535, so u16 never overflows (even worst case).

#define NBINS   57
#define NB3     171
#define TPB     512
#define NWARPS  16
#define HPW     (NB3 * 32)                 // halfwords per warp region = 5472
#define CNT_BYTES     (NWARPS * HPW * 2)   // 175,104
#define SCRATCH_INTS  (NWARPS * NB3)       // 2736
#define SMEM_BYTES    (CNT_BYTES + SCRATCH_INTS * 4)   // 186,048 B
#define MAXBLK  256

__device__ int g_part[NB3 * MAXBLK];       // [counter][block] for coalesced finalize

// One (p,t) pair: 3 counter increments. Ranges [0,57),[57,114),[114,171) are
// disjoint, so loads grouped before stores is exact and overlaps the RMW chains.
__device__ __forceinline__ void proc(unsigned short* __restrict__ wb, int p, int t) {
    unsigned short* aP = wb + (p << 5);
    unsigned short* aT = wb + ((57 + t) << 5);
    int m = (p == t) ? p : 0;               // mismatches land in inter[0] (unused)
    unsigned short* aI = wb + ((114 + m) << 5);
    unsigned short vP = *aP;
    unsigned short vT = *aT;
    unsigned short vI = *aI;
    *aP = (unsigned short)(vP + 1);
    *aT = (unsigned short)(vT + 1);
    *aI = (unsigned short)(vI + 1);
}

__device__ __forceinline__ void proc4(unsigned short* __restrict__ wb, int4 a, int4 b) {
    proc(wb, a.x, b.x);
    proc(wb, a.y, b.y);
    proc(wb, a.z, b.z);
    proc(wb, a.w, b.w);
}

extern "C" __global__ void __launch_bounds__(TPB, 1)
hist_kernel(const int* __restrict__ pred, const int* __restrict__ targ, int n)
{
    extern __shared__ int sh[];
    unsigned short* sh16 = (unsigned short*)sh;
    int* scratch = sh + (CNT_BYTES / 4);

    const int tid  = threadIdx.x;
    const int lane = tid & 31;
    const int warp = tid >> 5;
    unsigned short* wb = sh16 + warp * HPW + lane;

    // Zero counters + scratch.
    for (int i = tid; i < SMEM_BYTES / 4; i += TPB) sh[i] = 0;
    __syncthreads();

    const int stride = gridDim.x * TPB;

    const bool aligned = ((((uintptr_t)pred) | ((uintptr_t)targ)) & 15u) == 0;
    if (aligned) {
        const int n4 = n >> 2;
        const int4* __restrict__ p4 = (const int4*)pred;
        const int4* __restrict__ t4 = (const int4*)targ;
        int i = blockIdx.x * TPB + tid;

        // Main: 4 int4-pairs per thread per trip, all 8 loads issued up front
        // (LDG batch -> MLP=8/thread -> ~4KB in flight per warp).
        for (; i < n4 - 3 * stride; i += 4 * stride) {
            int4 a0 = __ldg(p4 + i);
            int4 a1 = __ldg(p4 + i + stride);
            int4 a2 = __ldg(p4 + i + 2 * stride);
            int4 a3 = __ldg(p4 + i + 3 * stride);
            int4 b0 = __ldg(t4 + i);
            int4 b1 = __ldg(t4 + i + stride);
            int4 b2 = __ldg(t4 + i + 2 * stride);
            int4 b3 = __ldg(t4 + i + 3 * stride);
            proc4(wb, a0, b0);
            proc4(wb, a1, b1);
            proc4(wb, a2, b2);
            proc4(wb, a3, b3);
        }
        for (; i < n4; i += stride) {
            int4 a = __ldg(p4 + i);
            int4 b = __ldg(t4 + i);
            proc4(wb, a, b);
        }
        for (int j = (n4 << 2) + blockIdx.x * TPB + tid; j < n; j += stride)
            proc(wb, __ldg(pred + j), __ldg(targ + j));
    } else {
        for (int i = blockIdx.x * TPB + tid; i < n; i += stride)
            proc(wb, __ldg(pred + i), __ldg(targ + i));
    }
    __syncthreads();

    // Per-warp lane reduction (conflict-free reads, REDUX.SUM folds 32 lanes).
    for (int c = 0; c < NB3; c++) {
        int v = (int)sh16[warp * HPW + c * 32 + lane];
        int s = __reduce_add_sync(0xffffffffu, v);
        if (lane == 0) scratch[warp * NB3 + c] = s;
    }
    __syncthreads();

    // Cross-warp sum -> per-block partial in [counter][block] layout
    // (fully overwritten every launch: deterministic, no atomics, no zeroing).
    if (tid < NB3) {
        int s = 0;
        #pragma unroll
        for (int w = 0; w < NWARPS; w++) s += scratch[w * NB3 + tid];
        g_part[tid * MAXBLK + blockIdx.x] = s;
    }
}

extern "C" __global__ void __launch_bounds__(1024)
final_kernel(float* __restrict__ out, int nblocks)
{
    __shared__ int   hh[NB3];
    __shared__ float dsum[64];
    const int tid  = threadIdx.x;
    const int lane = tid & 31;
    const int warp = tid >> 5;

    // 32 warps; warp handles counters warp, warp+32, ...
    // Lanes stride over blocks: coalesced loads, REDUX across lanes.
    for (int c = warp; c < NB3; c += 32) {
        int s = 0;
        for (int b = lane; b < nblocks; b += 32)
            s += g_part[c * MAXBLK + b];
        s = __reduce_add_sync(0xffffffffu, s);
        if (lane == 0) hh[c] = s;
    }
    __syncthreads();

    if (tid < 64) {
        float v = 0.0f;
        if (tid >= 1 && tid < NBINS) {
            float inter = (float)hh[114 + tid];
            float uni   = (float)hh[tid] + (float)hh[57 + tid];
            v = 2.0f * inter / (uni + 1e-5f);
        }
        dsum[tid] = v;
    }
    __syncthreads();

    if (tid == 0) {
        float s = 0.0f;
        #pragma unroll
        for (int i = 0; i < 64; i++) s += dsum[i];
        out[0] = 1.0f - s / (float)(NBINS - 1);
    }
}

extern "C" void kernel_launch(void* const* d_in, const int* in_sizes, int n_in,
                              void* d_out, int out_size)
{
    const int* pred = (const int*)d_in[0];
    const int* targ = (const int*)d_in[1];
    const int n = in_sizes[0];

    cudaFuncSetAttribute((const void*)hist_kernel,
                         cudaFuncAttributeMaxDynamicSharedMemorySize, SMEM_BYTES);

    int sms = 148;
    if (cudaDeviceGetAttribute(&sms, cudaDevAttrMultiProcessorCount, 0) != cudaSuccess)
        sms = 148;
    int grid = sms < MAXBLK ? sms : MAXBLK;
    if (grid < 1) grid = 1;

    hist_kernel<<<grid, TPB, SMEM_BYTES>>>(pred, targ, n);
    final_kernel<<<1, 1024>>>((float*)d_out, grid);
}